// round 14
// baseline (speedup 1.0000x reference)
#include <cuda_runtime.h>
#include <cuda_fp16.h>
#include <cstdint>

#define NOISE_SCALE (8.0f/255.0f)
#define K_SEL 64

__device__ float g_bias[256];                         // sum|w| * NOISE_SCALE
__device__ __half g_Aexp[2 * 9 * 256 * 128];          // [comp][kk][cout][cin]
__device__ float g_conv[(size_t)32 * 256 * 64 * 64];  // conv scratch (NCHW)

// ---------------- conv smem layout (bytes) ----------------
#define SM_AH  0                       // whi  [128 m][128 k] halves, 256B rows = 32KB
#define SM_AL  32768                   // wlo' [128 m][128 k] halves           = 32KB
#define SM_XH  65536                   // xh: 257 rows x 256B (row 0 zeros)    = 65792
#define SM_XL  131328                  // xl': 257 rows x 256B                 = 65792
#define XL_DELTA 65792
#define CONV_SMEM 197120               // 192.5KB

__device__ __forceinline__ uint32_t smem_u32(const void* p) {
    uint32_t a;
    asm("{ .reg .u64 t; cvta.to.shared.u64 t, %1; cvt.u32.u64 %0, t; }" : "=r"(a) : "l"(p));
    return a;
}
__device__ __forceinline__ unsigned ordmap(float f) {
    int s = __float_as_int(f);
    return (unsigned)(s ^ ((s >> 31) | 0x80000000));
}

#define CP_ASYNC16(dst, src) \
    asm volatile("cp.async.ca.shared.global [%0], [%1], 16;" :: "r"(dst), "l"(src))
#define CP_COMMIT() asm volatile("cp.async.commit_group;" ::: "memory")
#define CP_WAIT0()  asm volatile("cp.async.wait_group 0;" ::: "memory")

#define LDMX4(r0,r1,r2,r3,ad) \
    asm volatile("ldmatrix.sync.aligned.m8n8.x4.shared.b16 {%0,%1,%2,%3}, [%4];" \
        : "=r"(r0),"=r"(r1),"=r"(r2),"=r"(r3) : "r"(ad))
#define MMA16816(c, a, b0v, b1v) \
    asm volatile("mma.sync.aligned.m16n8k16.row.col.f32.f16.f16.f32 " \
        "{%0,%1,%2,%3}, {%4,%5,%6,%7}, {%8,%9}, {%0,%1,%2,%3};" \
        : "+f"((c)[0]), "+f"((c)[1]), "+f"((c)[2]), "+f"((c)[3]) \
        : "r"((a)[0]), "r"((a)[1]), "r"((a)[2]), "r"((a)[3]), "r"(b0v), "r"(b1v))

// ---------------- prep: g_bias[c] = NOISE_SCALE * sum |w[c,:,:,:]| ----------
__global__ void bias_kernel(const float* __restrict__ w) {
    int c = blockIdx.x, t = threadIdx.x;
    float s = 0.f;
    #pragma unroll
    for (int k = 0; k < 9; k++) s += fabsf(w[c * 1152 + k * 128 + t]);
    __shared__ float red[128];
    red[t] = s;
    __syncthreads();
    #pragma unroll
    for (int off = 64; off > 0; off >>= 1) {
        if (t < off) red[t] += red[t + off];
        __syncthreads();
    }
    if (t == 0) g_bias[c] = red[0] * NOISE_SCALE;
}

// ---------------- prep: fp16 hi/lo split weights ----------------
__global__ void wexpand_kernel(const float* __restrict__ w) {
    int co = blockIdx.x;
    for (int idx = threadIdx.x; idx < 1152; idx += blockDim.x) {
        int kk = idx >> 7, cin = idx & 127;
        float v = w[co * 1152 + cin * 9 + kk];
        __half hi = __float2half_rn(v);
        __half lo = __float2half_rn((v - __half2float(hi)) * 2048.0f);
        g_Aexp[((size_t)kk * 256 + co) * 128 + cin] = hi;
        g_Aexp[(size_t)9 * 256 * 128 + ((size_t)kk * 256 + co) * 128 + cin] = lo;
    }
}

// ---------------- conv: M=128 x N=128 stage-once fp16 mma.sync --------------
__global__ __launch_bounds__(256)
void conv_kernel(const float* __restrict__ x) {
    extern __shared__ char smem[];
    const uint32_t sb = smem_u32(smem);
    const int tid = threadIdx.x;
    const int wid = tid >> 5, lane = tid & 31;
    const int wm = wid & 3, wn = wid >> 2;       // 4 M-warps x 2 N-warps (N tile 64)
    const int mhalf = blockIdx.x;                // 0-1
    const int h0 = blockIdx.y * 2;               // 2 image rows per CTA
    const int b = blockIdx.z;                    // 0-31
    const int m0 = mhalf * 128;

    float acc1[2][8][4], acc2[2][8][4];
    #pragma unroll
    for (int i = 0; i < 2; i++)
        #pragma unroll
        for (int j = 0; j < 8; j++)
            #pragma unroll
            for (int k = 0; k < 4; k++) { acc1[i][j][k] = 0.f; acc2[i][j][k] = 0.f; }

    const int mlA = lane & 15, kbA = lane >> 4;               // A ldmatrix roles
    const int nloc = (lane & 7) + ((lane >> 4) & 1) * 8;      // B row-in-16 group
    const uint32_t kofb = (uint32_t)(((lane >> 3) & 1) * 16); // B 16B k-offset

    // ---- zero row 0 of both x buffers ----
    if (tid < 64) {
        *(uint32_t*)(smem + SM_XH + tid * 4) = 0u;
        *(uint32_t*)(smem + SM_XL + tid * 4) = 0u;
    }

    // ---- A staging roles; prefetch whi(kk=0) ----
    const int am = tid >> 1, aq = tid & 1;       // row am, k-half aq
    {
        const __half* Ac = g_Aexp + ((size_t)0 * 256 + m0 + am) * 128 + aq * 64;
        #pragma unroll
        for (int j = 0; j < 8; j++) {
            const uint32_t dst = sb + SM_AH + am * 256 +
                                 (uint32_t)(((aq * 8 + j) ^ (am & 7)) * 16);
            CP_ASYNC16(dst, Ac + j * 8);
        }
        CP_COMMIT();
    }

    // ---- stage x once: 4 image rows (h0-1..h0+2) x 128 cin, transposed ----
    {
        #pragma unroll 1
        for (int i = 0; i < 32; i++) {
            const int g = tid + 256 * i;          // 0..8191
            const int row = g >> 4;               // (slot, cin): 0..511
            const int f4i = g & 15;
            const int s = row >> 7, cin = row & 127;
            const int hh = h0 - 1 + s;
            if (hh < 0 || hh > 63) continue;
            float4 v = *(const float4*)(x + (((size_t)b * 128 + cin) * 64 + hh) * 64 + f4i * 4);
            float fv[4] = {v.x, v.y, v.z, v.w};
            const uint32_t colh = (uint32_t)(cin >> 3);
            const uint32_t cofs = (uint32_t)((cin & 7) * 2);
            #pragma unroll
            for (int e = 0; e < 4; e++) {
                const int w = f4i * 4 + e;
                const int smrow = 1 + s * 64 + w;
                const uint32_t ad = (uint32_t)(smrow * 256) +
                                    ((colh ^ (uint32_t)(smrow & 7)) * 16) + cofs;
                __half hi = __float2half_rn(fv[e]);
                __half lo = __float2half_rn((fv[e] - __half2float(hi)) * 2048.0f);
                *(__half*)(smem + SM_XH + ad) = hi;
                *(__half*)(smem + SM_XL + ad) = lo;
            }
        }
    }

    // ---- main loop over 9 taps ----
    #pragma unroll 1
    for (int kk = 0; kk < 9; kk++) {
        const int ky = kk / 3, kx = kk % 3;

        CP_WAIT0();
        __syncthreads();   // whi(kk) ready; x ready (kk=0); prior wlo reads done

        // prefetch wlo'(kk)
        {
            const __half* Ac = g_Aexp + (size_t)9 * 256 * 128
                             + ((size_t)kk * 256 + m0 + am) * 128 + aq * 64;
            #pragma unroll
            for (int j = 0; j < 8; j++) {
                const uint32_t dst = sb + SM_AL + am * 256 +
                                     (uint32_t)(((aq * 8 + j) ^ (am & 7)) * 16);
                CP_ASYNC16(dst, Ac + j * 8);
            }
            CP_COMMIT();
        }

        // per-lane B row addresses for this tap (r = wn)
        uint32_t baseH[4], par16[4];
        {
            const int hh = h0 + wn + ky - 1;
            const bool hv = (hh >= 0) && (hh < 64);
            const int s = wn + ky;
            #pragma unroll
            for (int p = 0; p < 4; p++) {
                const int w = p * 16 + nloc + kx - 1;
                const int rowidx = (hv && w >= 0 && w < 64) ? (1 + s * 64 + w) : 0;
                baseH[p] = sb + SM_XH + (uint32_t)(rowidx * 256);
                par16[p] = (uint32_t)((rowidx & 7) * 16);
            }
        }

        // ---- phase A: whi x (xh -> acc1, xl' -> acc2) ----
        #pragma unroll
        for (int ks = 0; ks < 8; ks++) {
            uint32_t ahi[2][4];
            #pragma unroll
            for (int mt = 0; mt < 2; mt++) {
                const int m = wm * 32 + mt * 16 + mlA;
                const uint32_t c = (uint32_t)(((ks * 2 + kbA) ^ (m & 7)) * 16);
                LDMX4(ahi[mt][0], ahi[mt][1], ahi[mt][2], ahi[mt][3],
                      sb + SM_AH + (uint32_t)(m * 256) + c);
            }
            #pragma unroll
            for (int p = 0; p < 4; p++) {
                const uint32_t adH = baseH[p] + (((uint32_t)(ks * 32) + kofb) ^ par16[p]);
                uint32_t bh[4], bl[4];
                LDMX4(bh[0], bh[1], bh[2], bh[3], adH);
                LDMX4(bl[0], bl[1], bl[2], bl[3], adH + XL_DELTA);
                #pragma unroll
                for (int mt = 0; mt < 2; mt++) {
                    MMA16816(acc1[mt][p * 2],     ahi[mt], bh[0], bh[1]);
                    MMA16816(acc1[mt][p * 2 + 1], ahi[mt], bh[2], bh[3]);
                    MMA16816(acc2[mt][p * 2],     ahi[mt], bl[0], bl[1]);
                    MMA16816(acc2[mt][p * 2 + 1], ahi[mt], bl[2], bl[3]);
                }
            }
        }

        CP_WAIT0();
        __syncthreads();   // wlo'(kk) ready; phase-A reads of SM_AH done

        // prefetch whi(kk+1)
        if (kk < 8) {
            const __half* Ac = g_Aexp + ((size_t)(kk + 1) * 256 + m0 + am) * 128 + aq * 64;
            #pragma unroll
            for (int j = 0; j < 8; j++) {
                const uint32_t dst = sb + SM_AH + am * 256 +
                                     (uint32_t)(((aq * 8 + j) ^ (am & 7)) * 16);
                CP_ASYNC16(dst, Ac + j * 8);
            }
            CP_COMMIT();
        }

        // ---- phase B: wlo' x xh -> acc2 ----
        #pragma unroll
        for (int ks = 0; ks < 8; ks++) {
            uint32_t alo[2][4];
            #pragma unroll
            for (int mt = 0; mt < 2; mt++) {
                const int m = wm * 32 + mt * 16 + mlA;
                const uint32_t c = (uint32_t)(((ks * 2 + kbA) ^ (m & 7)) * 16);
                LDMX4(alo[mt][0], alo[mt][1], alo[mt][2], alo[mt][3],
                      sb + SM_AL + (uint32_t)(m * 256) + c);
            }
            #pragma unroll
            for (int p = 0; p < 4; p++) {
                const uint32_t adH = baseH[p] + (((uint32_t)(ks * 32) + kofb) ^ par16[p]);
                uint32_t bh[4];
                LDMX4(bh[0], bh[1], bh[2], bh[3], adH);
                #pragma unroll
                for (int mt = 0; mt < 2; mt++) {
                    MMA16816(acc2[mt][p * 2],     alo[mt], bh[0], bh[1]);
                    MMA16816(acc2[mt][p * 2 + 1], alo[mt], bh[2], bh[3]);
                }
            }
        }
    }

    // ---- epilogue: combine and write conv scratch (row h0+wn) ----
    const float RS = 4.8828125e-4f;   // 2^-11
    #pragma unroll
    for (int mt = 0; mt < 2; mt++) {
        const int co = m0 + wm * 32 + mt * 16 + (lane >> 2);
        float* dst = g_conv + (((size_t)b * 256 + co) * 64 + (h0 + wn)) * 64;
        #pragma unroll
        for (int nt = 0; nt < 8; nt++) {
            const int n = nt * 8 + (lane & 3) * 2;
            float2 v01 = make_float2(acc1[mt][nt][0] + acc2[mt][nt][0] * RS,
                                     acc1[mt][nt][1] + acc2[mt][nt][1] * RS);
            float2 v23 = make_float2(acc1[mt][nt][2] + acc2[mt][nt][2] * RS,
                                     acc1[mt][nt][3] + acc2[mt][nt][3] * RS);
            *(float2*)(dst + n) = v01;
            *(float2*)(dst + 8 * 4096 + n) = v23;   // co + 8
        }
    }
}

// ---------------- topk: noise + 64th-largest + bias + relu ----------------
#define OS_FLOATS (64 * 257)
#define TOPK_SMEM ((OS_FLOATS + 64) * 4)

__global__ __launch_bounds__(512)
void topk_kernel(const float* __restrict__ noise,
                 const float* __restrict__ relu_bias,
                 float* __restrict__ out) {
    extern __shared__ float sm[];
    float* os = sm;                                  // [w][257]
    unsigned* th = (unsigned*)(sm + OS_FLOATS);      // [64]

    const int bh = blockIdx.x;
    const int b = bh >> 6;
    const int h = bh & 63;
    const int tid = threadIdx.x;
    const int wid = tid >> 5, lane = tid & 31;

    // load conv + noise add (g_bias pre-scaled by NOISE_SCALE)
    {
        const float* cb = g_conv + (size_t)b * 256 * 4096 + h * 64;
        const float* nb = noise + (size_t)b * 256 * 4096 + h * 64;
        for (int idx = tid; idx < 256 * 64; idx += 512) {
            int c = idx >> 6, w = idx & 63;
            float u = nb[c * 4096 + w];
            os[w * 257 + c] = fmaf(g_bias[c], 2.0f * u - 1.0f, cb[c * 4096 + w]);
        }
    }
    __syncthreads();

    // per-pixel 64th-largest: top-2 bounds + prefix-skipped bitwise radix select
    #pragma unroll 1
    for (int pp = 0; pp < 4; pp++) {
        const int p = wid * 4 + pp;
        unsigned uv[8];
        #pragma unroll
        for (int j = 0; j < 8; j++)
            uv[j] = ordmap(os[p * 257 + lane * 8 + j]);

        // per-lane top-2 (s0 >= s1)
        unsigned s0 = (uv[0] > uv[1]) ? uv[0] : uv[1];
        unsigned s1 = (uv[0] > uv[1]) ? uv[1] : uv[0];
        #pragma unroll
        for (int j = 2; j < 8; j++) {
            unsigned v = uv[j];
            unsigned t = (s0 < v) ? s0 : v;
            s0 = (s0 > v) ? s0 : v;
            s1 = (s1 > t) ? s1 : t;
        }
        // bounds: L = min_lane(s1) <= T <= U = max_lane(s1)
        const unsigned L = __reduce_min_sync(0xffffffffu, s1);
        const unsigned U = __reduce_max_sync(0xffffffffu, s1);

        unsigned X;
        if (L == U) {
            X = L;                       // T is pinned
        } else {
            const unsigned diff = L ^ U;
            const int hb = 31 - __clz(diff);
            X = (hb == 31) ? 0u : (U >> (hb + 1)) << (hb + 1);  // common prefix
            #pragma unroll 1
            for (int bit = hb; bit >= 0; bit--) {
                const unsigned cand = X | (1u << bit);
                int cnt = 0;
                #pragma unroll
                for (int j = 0; j < 8; j++) cnt += (uv[j] >= cand) ? 1 : 0;
                const int tot = __reduce_add_sync(0xffffffffu, cnt);
                if (tot >= K_SEL) X = cand;
            }
        }
        if (lane == 0) th[p] = X;
    }
    __syncthreads();

    // threshold + relu_bias + relu, coalesced store
    {
        float* ob = out + (size_t)b * 256 * 4096 + h * 64;
        for (int idx = tid; idx < 256 * 64; idx += 512) {
            int c = idx >> 6, w = idx & 63;
            float v = os[w * 257 + c];
            float keep = (ordmap(v) >= th[w]) ? v : 0.f;
            ob[c * 4096 + w] = fmaxf(keep + __ldg(relu_bias + c), 0.f);
        }
    }
}

// ---------------- launch (order chosen so ncu -s 5 lands on conv) ----------
extern "C" void kernel_launch(void* const* d_in, const int* in_sizes, int n_in,
                              void* d_out, int out_size) {
    const float* x         = (const float*)d_in[0];
    const float* weight    = (const float*)d_in[1];
    const float* relu_bias = (const float*)d_in[2];
    const float* noise     = (const float*)d_in[3];
    float* out = (float*)d_out;

    wexpand_kernel<<<256, 256>>>(weight);

    cudaFuncSetAttribute(conv_kernel,
                         cudaFuncAttributeMaxDynamicSharedMemorySize, CONV_SMEM);
    conv_kernel<<<dim3(2, 32, 32), 256, CONV_SMEM>>>(x);

    bias_kernel<<<256, 128>>>(weight);

    cudaFuncSetAttribute(topk_kernel,
                         cudaFuncAttributeMaxDynamicSharedMemorySize, TOPK_SMEM);
    topk_kernel<<<2048, 512, TOPK_SMEM>>>(noise, relu_bias, out);
}